// round 12
// baseline (speedup 1.0000x reference)
#include <cuda_runtime.h>
#include <cuda_bf16.h>
#include <cstdint>
#include <math.h>

// C = normalize_rows(ex) @ normalize_rows(ey)^T  [8192 x 8192]
// rowmax/colmax -> entropy terms. bf16 mma.sync GEMM, 128x64 CTA tile,
// 8 warps of 32x32, 3 CTAs/SM (24 warps/SM for tensor-pipe latency hiding),
// 3-stage cp.async, fused epilogue + finalize. C never materialized.

#define NROWS 8192
#define KDIM  768
#define BM 128
#define BN 64
#define BK 64                  // 64 bf16 = 128B rows
#define NK (KDIM / BK)         // 12
#define NSTAGE 3
#define A_BYTES (BM * BK * 2)  // 16384
#define B_BYTES (BN * BK * 2)  // 8192
#define STAGE_BYTES (A_BYTES + B_BYTES)     // 24576
#define SMEM_TOTAL (NSTAGE * STAGE_BYTES)   // 73728
#define NCTA ((NROWS / BM) * (NROWS / BN))  // 8192

__device__ __align__(128) __nv_bfloat16 g_Xn[NROWS * KDIM];
__device__ __align__(128) __nv_bfloat16 g_Yn[NROWS * KDIM];
__device__ float g_rowmax[NROWS];
__device__ float g_colmax[NROWS];
__device__ int g_done;

__device__ __forceinline__ void atomicMaxF(float* addr, float v) {
    if (v >= 0.f) atomicMax((int*)addr, __float_as_int(v));
    else          atomicMin((unsigned int*)addr, __float_as_uint(v));
}
__device__ __forceinline__ uint32_t s2u(const void* p) {
    return (uint32_t)__cvta_generic_to_shared(p);
}

// ---------------------------------------------------------------------------
// Kernel 1: row-normalize fp32 -> bf16 (warp/row) + init max arrays.
// ---------------------------------------------------------------------------
__global__ __launch_bounds__(256) void norm_kernel(const float* __restrict__ ex,
                                                   const float* __restrict__ ey) {
    if (threadIdx.x < 8) {
        int t = blockIdx.x * 8 + threadIdx.x;
        if (t < NROWS) g_rowmax[t] = -2.f;
        else           g_colmax[t - NROWS] = -2.f;
    }
    if (blockIdx.x == 0 && threadIdx.x == 8) g_done = 0;

    int warp = threadIdx.x >> 5, lane = threadIdx.x & 31;
    int row = blockIdx.x * 8 + warp;
    const float* src;
    __nv_bfloat16* dst;
    if (row < NROWS) { src = ex + (size_t)row * KDIM; dst = g_Xn + (size_t)row * KDIM; }
    else { row -= NROWS; src = ey + (size_t)row * KDIM; dst = g_Yn + (size_t)row * KDIM; }

    float4 v[6];
    float ss = 0.f;
    #pragma unroll
    for (int w = 0; w < 6; w++) {
        v[w] = ((const float4*)src)[lane + w * 32];
        ss += v[w].x * v[w].x + v[w].y * v[w].y + v[w].z * v[w].z + v[w].w * v[w].w;
    }
    #pragma unroll
    for (int o = 16; o > 0; o >>= 1) ss += __shfl_xor_sync(0xffffffffu, ss, o);
    float inv = 1.0f / fmaxf(sqrtf(ss), 1e-8f);
    #pragma unroll
    for (int w = 0; w < 6; w++) {
        __nv_bfloat162 lo = __floats2bfloat162_rn(v[w].x * inv, v[w].y * inv);
        __nv_bfloat162 hi = __floats2bfloat162_rn(v[w].z * inv, v[w].w * inv);
        uint2 packed;
        packed.x = *(uint32_t*)&lo;
        packed.y = *(uint32_t*)&hi;
        ((uint2*)dst)[lane + w * 32] = packed;
    }
}

// ---------------------------------------------------------------------------
// Kernel 2: bf16 GEMM, 128x64 CTA tile, 8 warps (32x32 each, 4x2 layout),
// BK=64, 3-stage cp.async (one barrier/iter), 3 CTAs/SM,
// fused row/col max + finalize.
// Swizzle: sw(row, kh) = row*128 + ((kh ^ (row & 7)) << 4), kh = 16B chunk.
// ---------------------------------------------------------------------------
__global__ __launch_bounds__(256, 3) void gemm_max_kernel(float* __restrict__ out) {
    extern __shared__ __align__(1024) char smem[];
    __shared__ float srow[BM];
    __shared__ float scol[BN];
    __shared__ int is_last;

    const int tid = threadIdx.x;
    const int warp = tid >> 5, lane = tid & 31;
    const int m0 = blockIdx.y * BM;
    const int n0 = blockIdx.x * BN;
    const int wm = (warp >> 1) * 32;   // 0,32,64,96
    const int wn = (warp & 1) * 32;    // 0 or 32

    if (tid < BM) srow[tid] = -2.f;
    if (tid < BN) scol[tid] = -2.f;

    float acc[2][4][4];
    #pragma unroll
    for (int a = 0; a < 2; a++)
        #pragma unroll
        for (int b = 0; b < 4; b++)
            #pragma unroll
            for (int c = 0; c < 4; c++) acc[a][b][c] = 0.f;

    auto prefetch = [&](int stage, int k0, bool valid) {
        if (valid) {
            char* sa = smem + stage * STAGE_BYTES;
            char* sb = sa + A_BYTES;
            #pragma unroll
            for (int j = 0; j < 6; j++) {
                int i = tid + j * 256;  // 0..1535 chunks of 16B
                const __nv_bfloat16* src;
                uint32_t dst;
                if (i < 1024) {         // A: 128 rows x 8 chunks
                    int row = i >> 3, kh = i & 7;
                    src = g_Xn + (size_t)(m0 + row) * KDIM + k0 + kh * 8;
                    dst = s2u(sa + row * 128 + ((kh ^ (row & 7)) << 4));
                } else {                // B: 64 rows x 8 chunks
                    int idx = i - 1024;
                    int row = idx >> 3, kh = idx & 7;
                    src = g_Yn + (size_t)(n0 + row) * KDIM + k0 + kh * 8;
                    dst = s2u(sb + row * 128 + ((kh ^ (row & 7)) << 4));
                }
                asm volatile("cp.async.cg.shared.global [%0], [%1], 16;"
                             :: "r"(dst), "l"(src));
            }
        }
        asm volatile("cp.async.commit_group;");
    };

    prefetch(0, 0, true);
    prefetch(1, BK, true);

    int stage = 0;
    for (int it = 0; it < NK; it++) {
        asm volatile("cp.async.wait_group 1;");
        __syncthreads();
        // Stage (stage+2)%3 was consumed at iter it-1; safe to overwrite.
        prefetch((stage + 2) % NSTAGE, (it + 2) * BK, it + 2 < NK);

        const uint32_t sa = s2u(smem) + (uint32_t)stage * STAGE_BYTES;
        const uint32_t sb = sa + A_BYTES;

        #pragma unroll
        for (int kk = 0; kk < 4; kk++) {
            uint32_t af[2][4], bf[2][4];
            #pragma unroll
            for (int mt = 0; mt < 2; mt++) {
                int row = wm + mt * 16 + (lane & 15);
                int kh = kk * 2 + (lane >> 4);
                uint32_t addr = sa + row * 128 + ((kh ^ (row & 7)) << 4);
                asm volatile(
                    "ldmatrix.sync.aligned.m8n8.x4.shared.b16 {%0,%1,%2,%3}, [%4];"
                    : "=r"(af[mt][0]), "=r"(af[mt][1]),
                      "=r"(af[mt][2]), "=r"(af[mt][3]) : "r"(addr));
            }
            #pragma unroll
            for (int p = 0; p < 2; p++) {
                int n = wn + p * 16 + ((lane >> 4) << 3) + (lane & 7);
                int kh = kk * 2 + ((lane >> 3) & 1);
                uint32_t addr = sb + n * 128 + ((kh ^ (n & 7)) << 4);
                asm volatile(
                    "ldmatrix.sync.aligned.m8n8.x4.shared.b16 {%0,%1,%2,%3}, [%4];"
                    : "=r"(bf[p][0]), "=r"(bf[p][1]),
                      "=r"(bf[p][2]), "=r"(bf[p][3]) : "r"(addr));
            }
            #pragma unroll
            for (int mt = 0; mt < 2; mt++)
                #pragma unroll
                for (int nt = 0; nt < 4; nt++) {
                    asm volatile(
                        "mma.sync.aligned.m16n8k16.row.col.f32.bf16.bf16.f32 "
                        "{%0,%1,%2,%3}, {%4,%5,%6,%7}, {%8,%9}, {%0,%1,%2,%3};\n"
                        : "+f"(acc[mt][nt][0]), "+f"(acc[mt][nt][1]),
                          "+f"(acc[mt][nt][2]), "+f"(acc[mt][nt][3])
                        : "r"(af[mt][0]), "r"(af[mt][1]),
                          "r"(af[mt][2]), "r"(af[mt][3]),
                          "r"(bf[nt >> 1][(nt & 1) * 2]),
                          "r"(bf[nt >> 1][(nt & 1) * 2 + 1]));
                }
        }
        stage = (stage + 1 == NSTAGE) ? 0 : stage + 1;
    }
    __syncthreads();

    const int g = lane >> 2, tig = lane & 3;
    // ---- row maxes: row = wm + mt*16 + g + p*8 ----
    #pragma unroll
    for (int mt = 0; mt < 2; mt++)
        #pragma unroll
        for (int p = 0; p < 2; p++) {
            float m = -2.f;
            #pragma unroll
            for (int nt = 0; nt < 4; nt++) {
                m = fmaxf(m, acc[mt][nt][p * 2 + 0]);
                m = fmaxf(m, acc[mt][nt][p * 2 + 1]);
            }
            m = fmaxf(m, __shfl_xor_sync(0xffffffffu, m, 1));
            m = fmaxf(m, __shfl_xor_sync(0xffffffffu, m, 2));
            if (tig == 0) atomicMaxF(&srow[wm + mt * 16 + g + p * 8], m);
        }
    // ---- col maxes: col = wn + nt*8 + tig*2 + q ----
    #pragma unroll
    for (int nt = 0; nt < 4; nt++)
        #pragma unroll
        for (int q = 0; q < 2; q++) {
            float m = fmaxf(fmaxf(acc[0][nt][q], acc[0][nt][2 + q]),
                            fmaxf(acc[1][nt][q], acc[1][nt][2 + q]));
            m = fmaxf(m, __shfl_xor_sync(0xffffffffu, m, 4));
            m = fmaxf(m, __shfl_xor_sync(0xffffffffu, m, 8));
            m = fmaxf(m, __shfl_xor_sync(0xffffffffu, m, 16));
            if (g == 0) atomicMaxF(&scol[wn + nt * 8 + tig * 2 + q], m);
        }

    __syncthreads();
    if (tid < BM) atomicMaxF(&g_rowmax[m0 + tid], srow[tid]);
    if (tid < BN) atomicMaxF(&g_colmax[n0 + tid], scol[tid]);

    // ---- fused finalize: last CTA computes the entropy sums ----
    __threadfence();
    if (tid == 0) is_last = (atomicAdd(&g_done, 1) == NCTA - 1) ? 1 : 0;
    __syncthreads();
    if (!is_last) return;

    const float LOG_NORM = -0.69579514f;  // -log(0.8) - 0.5*log(2*pi)
    const float INV2S2   = 0.78125f;      // 1 / (2 * 0.8^2)
    float s1 = 0.f, s2 = 0.f;
    for (int i = tid; i < NROWS; i += 256) {
        float c = __int_as_float(__ldcg((int*)&g_rowmax[i]));
        float lp = -(c * c) * INV2S2 + LOG_NORM;
        s1 -= __expf(lp) * lp;
        c = __int_as_float(__ldcg((int*)&g_colmax[i]));
        lp = -(c * c) * INV2S2 + LOG_NORM;
        s2 -= __expf(lp) * lp;
    }
    #pragma unroll
    for (int o = 16; o > 0; o >>= 1) {
        s1 += __shfl_xor_sync(0xffffffffu, s1, o);
        s2 += __shfl_xor_sync(0xffffffffu, s2, o);
    }
    __shared__ float w1[8], w2[8];
    if ((tid & 31) == 0) { w1[tid >> 5] = s1; w2[tid >> 5] = s2; }
    __syncthreads();
    if (tid == 0) {
        float t1 = 0.f, t2 = 0.f;
        #pragma unroll
        for (int i = 0; i < 8; i++) { t1 += w1[i]; t2 += w2[i]; }
        out[0] = t1;
        out[1] = t2;
    }
}

// ---------------------------------------------------------------------------
extern "C" void kernel_launch(void* const* d_in, const int* in_sizes, int n_in,
                              void* d_out, int out_size) {
    (void)in_sizes; (void)n_in; (void)out_size;
    const float* ex = (const float*)d_in[0];
    const float* ey = (const float*)d_in[1];
    float* out = (float*)d_out;

    cudaFuncSetAttribute(gemm_max_kernel,
                         cudaFuncAttributeMaxDynamicSharedMemorySize, SMEM_TOTAL);

    norm_kernel<<<2 * NROWS / 8, 256>>>(ex, ey);
    dim3 grid(NROWS / BN, NROWS / BM);   // 128 x 64
    gemm_max_kernel<<<grid, 256, SMEM_TOTAL>>>(out);
}

// round 13
// speedup vs baseline: 1.0996x; 1.0996x over previous
#include <cuda_runtime.h>
#include <cuda_bf16.h>
#include <cstdint>
#include <math.h>

// C = normalize_rows(ex) @ normalize_rows(ey)^T  [8192 x 8192]
// rowmax/colmax -> entropy terms. bf16 mma.sync GEMM, 128x64 CTA tile,
// 4 warps of 64x32, 4 CTAs/SM (16 warps/SM in 4 independent barrier
// domains), 2-stage cp.async, fused epilogue + finalize.

#define NROWS 8192
#define KDIM  768
#define BM 128
#define BN 64
#define BK 64                  // 64 bf16 = 128B rows
#define NK (KDIM / BK)         // 12
#define NSTAGE 2
#define A_BYTES (BM * BK * 2)  // 16384
#define B_BYTES (BN * BK * 2)  // 8192
#define STAGE_BYTES (A_BYTES + B_BYTES)     // 24576
#define SMEM_TOTAL (NSTAGE * STAGE_BYTES)   // 49152
#define NCTA ((NROWS / BM) * (NROWS / BN))  // 8192

__device__ __align__(128) __nv_bfloat16 g_Xn[NROWS * KDIM];
__device__ __align__(128) __nv_bfloat16 g_Yn[NROWS * KDIM];
__device__ float g_rowmax[NROWS];
__device__ float g_colmax[NROWS];
__device__ int g_done;

__device__ __forceinline__ void atomicMaxF(float* addr, float v) {
    if (v >= 0.f) atomicMax((int*)addr, __float_as_int(v));
    else          atomicMin((unsigned int*)addr, __float_as_uint(v));
}
__device__ __forceinline__ uint32_t s2u(const void* p) {
    return (uint32_t)__cvta_generic_to_shared(p);
}

// ---------------------------------------------------------------------------
// Kernel 1: row-normalize fp32 -> bf16 (warp/row) + init max arrays.
// ---------------------------------------------------------------------------
__global__ __launch_bounds__(256) void norm_kernel(const float* __restrict__ ex,
                                                   const float* __restrict__ ey) {
    if (threadIdx.x < 8) {
        int t = blockIdx.x * 8 + threadIdx.x;
        if (t < NROWS) g_rowmax[t] = -2.f;
        else           g_colmax[t - NROWS] = -2.f;
    }
    if (blockIdx.x == 0 && threadIdx.x == 8) g_done = 0;

    int warp = threadIdx.x >> 5, lane = threadIdx.x & 31;
    int row = blockIdx.x * 8 + warp;
    const float* src;
    __nv_bfloat16* dst;
    if (row < NROWS) { src = ex + (size_t)row * KDIM; dst = g_Xn + (size_t)row * KDIM; }
    else { row -= NROWS; src = ey + (size_t)row * KDIM; dst = g_Yn + (size_t)row * KDIM; }

    float4 v[6];
    float ss = 0.f;
    #pragma unroll
    for (int w = 0; w < 6; w++) {
        v[w] = ((const float4*)src)[lane + w * 32];
        ss += v[w].x * v[w].x + v[w].y * v[w].y + v[w].z * v[w].z + v[w].w * v[w].w;
    }
    #pragma unroll
    for (int o = 16; o > 0; o >>= 1) ss += __shfl_xor_sync(0xffffffffu, ss, o);
    float inv = 1.0f / fmaxf(sqrtf(ss), 1e-8f);
    #pragma unroll
    for (int w = 0; w < 6; w++) {
        __nv_bfloat162 lo = __floats2bfloat162_rn(v[w].x * inv, v[w].y * inv);
        __nv_bfloat162 hi = __floats2bfloat162_rn(v[w].z * inv, v[w].w * inv);
        uint2 packed;
        packed.x = *(uint32_t*)&lo;
        packed.y = *(uint32_t*)&hi;
        ((uint2*)dst)[lane + w * 32] = packed;
    }
}

// ---------------------------------------------------------------------------
// Kernel 2: bf16 GEMM, 128x64 CTA tile, 4 warps (64x32 each, 2x2 layout),
// BK=64, 2-stage cp.async, 4 CTAs/SM, fused row/col max + finalize.
// Swizzle: sw(row, kh) = row*128 + ((kh ^ (row & 7)) << 4), kh = 16B chunk.
// ---------------------------------------------------------------------------
__global__ __launch_bounds__(128, 4) void gemm_max_kernel(float* __restrict__ out) {
    extern __shared__ __align__(1024) char smem[];
    __shared__ float srow[BM];
    __shared__ float scol[BN];
    __shared__ int is_last;

    const int tid = threadIdx.x;
    const int warp = tid >> 5, lane = tid & 31;
    const int m0 = blockIdx.y * BM;
    const int n0 = blockIdx.x * BN;
    const int wm = (warp >> 1) * 64;   // 0 or 64
    const int wn = (warp & 1) * 32;    // 0 or 32

    if (tid < BM) srow[tid] = -2.f;
    if (tid < BN) scol[tid] = -2.f;

    float acc[4][4][4];
    #pragma unroll
    for (int a = 0; a < 4; a++)
        #pragma unroll
        for (int b = 0; b < 4; b++)
            #pragma unroll
            for (int c = 0; c < 4; c++) acc[a][b][c] = 0.f;

    auto prefetch = [&](int stage, int k0, bool valid) {
        if (valid) {
            char* sa = smem + stage * STAGE_BYTES;
            char* sb = sa + A_BYTES;
            #pragma unroll
            for (int j = 0; j < 12; j++) {
                int i = tid + j * 128;  // 0..1535 chunks of 16B
                const __nv_bfloat16* src;
                uint32_t dst;
                if (i < 1024) {         // A: 128 rows x 8 chunks
                    int row = i >> 3, kh = i & 7;
                    src = g_Xn + (size_t)(m0 + row) * KDIM + k0 + kh * 8;
                    dst = s2u(sa + row * 128 + ((kh ^ (row & 7)) << 4));
                } else {                // B: 64 rows x 8 chunks
                    int idx = i - 1024;
                    int row = idx >> 3, kh = idx & 7;
                    src = g_Yn + (size_t)(n0 + row) * KDIM + k0 + kh * 8;
                    dst = s2u(sb + row * 128 + ((kh ^ (row & 7)) << 4));
                }
                asm volatile("cp.async.cg.shared.global [%0], [%1], 16;"
                             :: "r"(dst), "l"(src));
            }
        }
        asm volatile("cp.async.commit_group;");
    };

    prefetch(0, 0, true);

    for (int it = 0; it < NK; it++) {
        asm volatile("cp.async.wait_group 0;");
        __syncthreads();
        // Stage being overwritten was consumed last iter (trailing barrier).
        prefetch((it + 1) & 1, (it + 1) * BK, it + 1 < NK);

        const uint32_t sa = s2u(smem) + (uint32_t)(it & 1) * STAGE_BYTES;
        const uint32_t sb = sa + A_BYTES;

        #pragma unroll
        for (int kk = 0; kk < 4; kk++) {
            uint32_t af[4][4], bf[2][4];
            #pragma unroll
            for (int mt = 0; mt < 4; mt++) {
                int row = wm + mt * 16 + (lane & 15);
                int kh = kk * 2 + (lane >> 4);
                uint32_t addr = sa + row * 128 + ((kh ^ (row & 7)) << 4);
                asm volatile(
                    "ldmatrix.sync.aligned.m8n8.x4.shared.b16 {%0,%1,%2,%3}, [%4];"
                    : "=r"(af[mt][0]), "=r"(af[mt][1]),
                      "=r"(af[mt][2]), "=r"(af[mt][3]) : "r"(addr));
            }
            #pragma unroll
            for (int p = 0; p < 2; p++) {
                int n = wn + p * 16 + ((lane >> 4) << 3) + (lane & 7);
                int kh = kk * 2 + ((lane >> 3) & 1);
                uint32_t addr = sb + n * 128 + ((kh ^ (n & 7)) << 4);
                asm volatile(
                    "ldmatrix.sync.aligned.m8n8.x4.shared.b16 {%0,%1,%2,%3}, [%4];"
                    : "=r"(bf[p][0]), "=r"(bf[p][1]),
                      "=r"(bf[p][2]), "=r"(bf[p][3]) : "r"(addr));
            }
            #pragma unroll
            for (int mt = 0; mt < 4; mt++)
                #pragma unroll
                for (int nt = 0; nt < 4; nt++) {
                    asm volatile(
                        "mma.sync.aligned.m16n8k16.row.col.f32.bf16.bf16.f32 "
                        "{%0,%1,%2,%3}, {%4,%5,%6,%7}, {%8,%9}, {%0,%1,%2,%3};\n"
                        : "+f"(acc[mt][nt][0]), "+f"(acc[mt][nt][1]),
                          "+f"(acc[mt][nt][2]), "+f"(acc[mt][nt][3])
                        : "r"(af[mt][0]), "r"(af[mt][1]),
                          "r"(af[mt][2]), "r"(af[mt][3]),
                          "r"(bf[nt >> 1][(nt & 1) * 2]),
                          "r"(bf[nt >> 1][(nt & 1) * 2 + 1]));
                }
        }
        __syncthreads();
    }

    const int g = lane >> 2, tig = lane & 3;
    // ---- row maxes: row = wm + mt*16 + g + p*8 ----
    #pragma unroll
    for (int mt = 0; mt < 4; mt++)
        #pragma unroll
        for (int p = 0; p < 2; p++) {
            float m = -2.f;
            #pragma unroll
            for (int nt = 0; nt < 4; nt++) {
                m = fmaxf(m, acc[mt][nt][p * 2 + 0]);
                m = fmaxf(m, acc[mt][nt][p * 2 + 1]);
            }
            m = fmaxf(m, __shfl_xor_sync(0xffffffffu, m, 1));
            m = fmaxf(m, __shfl_xor_sync(0xffffffffu, m, 2));
            if (tig == 0) atomicMaxF(&srow[wm + mt * 16 + g + p * 8], m);
        }
    // ---- col maxes: col = wn + nt*8 + tig*2 + q ----
    #pragma unroll
    for (int nt = 0; nt < 4; nt++)
        #pragma unroll
        for (int q = 0; q < 2; q++) {
            float m = -2.f;
            #pragma unroll
            for (int mt = 0; mt < 4; mt++) {
                m = fmaxf(m, acc[mt][nt][q]);
                m = fmaxf(m, acc[mt][nt][2 + q]);
            }
            m = fmaxf(m, __shfl_xor_sync(0xffffffffu, m, 4));
            m = fmaxf(m, __shfl_xor_sync(0xffffffffu, m, 8));
            m = fmaxf(m, __shfl_xor_sync(0xffffffffu, m, 16));
            if (g == 0) atomicMaxF(&scol[wn + nt * 8 + tig * 2 + q], m);
        }

    __syncthreads();
    if (tid < BM) atomicMaxF(&g_rowmax[m0 + tid], srow[tid]);
    if (tid < BN) atomicMaxF(&g_colmax[n0 + tid], scol[tid]);

    // ---- fused finalize: last CTA computes the entropy sums ----
    __threadfence();
    if (tid == 0) is_last = (atomicAdd(&g_done, 1) == NCTA - 1) ? 1 : 0;
    __syncthreads();
    if (!is_last) return;

    const float LOG_NORM = -0.69579514f;  // -log(0.8) - 0.5*log(2*pi)
    const float INV2S2   = 0.78125f;      // 1 / (2 * 0.8^2)
    float s1 = 0.f, s2 = 0.f;
    for (int i = tid; i < NROWS; i += 128) {
        float c = __int_as_float(__ldcg((int*)&g_rowmax[i]));
        float lp = -(c * c) * INV2S2 + LOG_NORM;
        s1 -= __expf(lp) * lp;
        c = __int_as_float(__ldcg((int*)&g_colmax[i]));
        lp = -(c * c) * INV2S2 + LOG_NORM;
        s2 -= __expf(lp) * lp;
    }
    #pragma unroll
    for (int o = 16; o > 0; o >>= 1) {
        s1 += __shfl_xor_sync(0xffffffffu, s1, o);
        s2 += __shfl_xor_sync(0xffffffffu, s2, o);
    }
    __shared__ float w1[4], w2[4];
    if ((tid & 31) == 0) { w1[tid >> 5] = s1; w2[tid >> 5] = s2; }
    __syncthreads();
    if (tid == 0) {
        out[0] = w1[0] + w1[1] + w1[2] + w1[3];
        out[1] = w2[0] + w2[1] + w2[2] + w2[3];
    }
}

// ---------------------------------------------------------------------------
extern "C" void kernel_launch(void* const* d_in, const int* in_sizes, int n_in,
                              void* d_out, int out_size) {
    (void)in_sizes; (void)n_in; (void)out_size;
    const float* ex = (const float*)d_in[0];
    const float* ey = (const float*)d_in[1];
    float* out = (float*)d_out;

    cudaFuncSetAttribute(gemm_max_kernel,
                         cudaFuncAttributeMaxDynamicSharedMemorySize, SMEM_TOTAL);

    norm_kernel<<<2 * NROWS / 8, 256>>>(ex, ey);
    dim3 grid(NROWS / BN, NROWS / BM);   // 128 x 64
    gemm_max_kernel<<<grid, 128, SMEM_TOTAL>>>(out);
}

// round 15
// speedup vs baseline: 1.1271x; 1.0250x over previous
#include <cuda_runtime.h>
#include <cuda_fp16.h>
#include <cstdint>
#include <math.h>

// C = normalize_rows(ex) @ normalize_rows(ey)^T  [8192 x 8192]
// rowmax/colmax -> entropy terms. f16 mma.sync GEMM with F16 ACCUMULATORS
// (64x64 warp tile acc = 64 regs -> room for fragment double buffering),
// 128x256 CTA tile, 2 CTAs/SM, 2-stage cp.async, fused epilogue + finalize.

#define NROWS 8192
#define KDIM  768
#define BM 128
#define BN 256
#define BK 64                  // 64 f16 = 128B rows
#define NK (KDIM / BK)         // 12
#define A_BYTES (BM * BK * 2)  // 16384
#define B_BYTES (BN * BK * 2)  // 32768
#define STAGE_BYTES (A_BYTES + B_BYTES)     // 49152
#define SMEM_TOTAL (2 * STAGE_BYTES)        // 98304
#define NCTA ((NROWS / BM) * (NROWS / BN))  // 2048

__device__ __align__(128) __half g_Xn[NROWS * KDIM];
__device__ __align__(128) __half g_Yn[NROWS * KDIM];
__device__ float g_rowmax[NROWS];
__device__ float g_colmax[NROWS];
__device__ int g_done;

__device__ __forceinline__ void atomicMaxF(float* addr, float v) {
    if (v >= 0.f) atomicMax((int*)addr, __float_as_int(v));
    else          atomicMin((unsigned int*)addr, __float_as_uint(v));
}
__device__ __forceinline__ uint32_t s2u(const void* p) {
    return (uint32_t)__cvta_generic_to_shared(p);
}

// ---------------------------------------------------------------------------
// Kernel 1: row-normalize fp32 -> f16 (warp/row) + init max arrays.
// ---------------------------------------------------------------------------
__global__ __launch_bounds__(256) void norm_kernel(const float* __restrict__ ex,
                                                   const float* __restrict__ ey) {
    if (threadIdx.x < 8) {
        int t = blockIdx.x * 8 + threadIdx.x;
        if (t < NROWS) g_rowmax[t] = -2.f;
        else           g_colmax[t - NROWS] = -2.f;
    }
    if (blockIdx.x == 0 && threadIdx.x == 8) g_done = 0;

    int warp = threadIdx.x >> 5, lane = threadIdx.x & 31;
    int row = blockIdx.x * 8 + warp;
    const float* src;
    __half* dst;
    if (row < NROWS) { src = ex + (size_t)row * KDIM; dst = g_Xn + (size_t)row * KDIM; }
    else { row -= NROWS; src = ey + (size_t)row * KDIM; dst = g_Yn + (size_t)row * KDIM; }

    float4 v[6];
    float ss = 0.f;
    #pragma unroll
    for (int w = 0; w < 6; w++) {
        v[w] = ((const float4*)src)[lane + w * 32];
        ss += v[w].x * v[w].x + v[w].y * v[w].y + v[w].z * v[w].z + v[w].w * v[w].w;
    }
    #pragma unroll
    for (int o = 16; o > 0; o >>= 1) ss += __shfl_xor_sync(0xffffffffu, ss, o);
    float inv = 1.0f / fmaxf(sqrtf(ss), 1e-8f);
    #pragma unroll
    for (int w = 0; w < 6; w++) {
        __half2 lo = __floats2half2_rn(v[w].x * inv, v[w].y * inv);
        __half2 hi = __floats2half2_rn(v[w].z * inv, v[w].w * inv);
        uint2 packed;
        packed.x = *(uint32_t*)&lo;
        packed.y = *(uint32_t*)&hi;
        ((uint2*)dst)[lane + w * 32] = packed;
    }
}

// ---------------------------------------------------------------------------
// Kernel 2: f16 GEMM (f16 acc), 128x256 CTA tile, 8 warps = 2(m) x 4(n) of
// 64x64 tiles, BK=64, fragment double buffering, 2-stage cp.async,
// 2 CTAs/SM, fused row/col max + finalize.
// Swizzle: sw(row, kh) = row*128 + ((kh ^ (row & 7)) << 4), kh = 16B chunk.
// ---------------------------------------------------------------------------
__global__ __launch_bounds__(256, 2) void gemm_max_kernel(float* __restrict__ out) {
    extern __shared__ __align__(1024) char smem[];
    __shared__ float srow[BM];
    __shared__ float scol[BN];
    __shared__ int is_last;

    const int tid = threadIdx.x;
    const int warp = tid >> 5, lane = tid & 31;
    const int m0 = blockIdx.y * BM;
    const int n0 = blockIdx.x * BN;
    const int wm = (warp >> 2) * 64;      // 0 or 64
    const int wn64 = (warp & 3) * 64;     // 0,64,128,192

    if (tid < BM) srow[tid] = -2.f;
    if (tid < BN) scol[tid] = -2.f;

    // 64x64 warp tile, f16 acc: 4 mt x 8 nt x 2 regs = 64 regs.
    uint32_t acc[4][8][2];
    #pragma unroll
    for (int a = 0; a < 4; a++)
        #pragma unroll
        for (int b = 0; b < 8; b++) { acc[a][b][0] = 0u; acc[a][b][1] = 0u; }

    auto prefetch = [&](int stage, int k0, bool valid) {
        if (valid) {
            char* sa = smem + stage * STAGE_BYTES;
            char* sb = sa + A_BYTES;
            #pragma unroll
            for (int j = 0; j < 12; j++) {
                int i = tid + j * 256;  // 0..3071 chunks of 16B
                const __half* src;
                uint32_t dst;
                if (i < 1024) {         // A: 128 rows x 8 chunks
                    int row = i >> 3, kh = i & 7;
                    src = g_Xn + (size_t)(m0 + row) * KDIM + k0 + kh * 8;
                    dst = s2u(sa + row * 128 + ((kh ^ (row & 7)) << 4));
                } else {                // B: 256 rows x 8 chunks
                    int idx = i - 1024;
                    int row = idx >> 3, kh = idx & 7;
                    src = g_Yn + (size_t)(n0 + row) * KDIM + k0 + kh * 8;
                    dst = s2u(sb + row * 128 + ((kh ^ (row & 7)) << 4));
                }
                asm volatile("cp.async.cg.shared.global [%0], [%1], 16;"
                             :: "r"(dst), "l"(src));
            }
        }
        asm volatile("cp.async.commit_group;");
    };

    prefetch(0, 0, true);

    uint32_t af[2][4][4], bf[2][4][4];

    auto load_frags = [&](uint32_t sa, uint32_t sb, int kk, int buf) {
        #pragma unroll
        for (int mt = 0; mt < 4; mt++) {
            int row = wm + mt * 16 + (lane & 15);
            int kh = kk * 2 + (lane >> 4);
            uint32_t addr = sa + row * 128 + ((kh ^ (row & 7)) << 4);
            asm volatile(
                "ldmatrix.sync.aligned.m8n8.x4.shared.b16 {%0,%1,%2,%3}, [%4];"
                : "=r"(af[buf][mt][0]), "=r"(af[buf][mt][1]),
                  "=r"(af[buf][mt][2]), "=r"(af[buf][mt][3]) : "r"(addr));
        }
        #pragma unroll
        for (int p = 0; p < 4; p++) {
            int n = wn64 + p * 16 + ((lane >> 4) << 3) + (lane & 7);
            int kh = kk * 2 + ((lane >> 3) & 1);
            uint32_t addr = sb + n * 128 + ((kh ^ (n & 7)) << 4);
            asm volatile(
                "ldmatrix.sync.aligned.m8n8.x4.shared.b16 {%0,%1,%2,%3}, [%4];"
                : "=r"(bf[buf][p][0]), "=r"(bf[buf][p][1]),
                  "=r"(bf[buf][p][2]), "=r"(bf[buf][p][3]) : "r"(addr));
        }
    };

    for (int it = 0; it < NK; it++) {
        asm volatile("cp.async.wait_group 0;");
        __syncthreads();
        prefetch((it + 1) & 1, (it + 1) * BK, it + 1 < NK);

        const uint32_t sa = s2u(smem) + (uint32_t)(it & 1) * STAGE_BYTES;
        const uint32_t sb = sa + A_BYTES;

        load_frags(sa, sb, 0, 0);
        #pragma unroll
        for (int kk = 0; kk < 4; kk++) {
            if (kk < 3) load_frags(sa, sb, kk + 1, (kk + 1) & 1);
            const int b = kk & 1;
            #pragma unroll
            for (int mt = 0; mt < 4; mt++)
                #pragma unroll
                for (int nt = 0; nt < 8; nt++) {
                    asm volatile(
                        "mma.sync.aligned.m16n8k16.row.col.f16.f16.f16.f16 "
                        "{%0,%1}, {%2,%3,%4,%5}, {%6,%7}, {%0,%1};\n"
                        : "+r"(acc[mt][nt][0]), "+r"(acc[mt][nt][1])
                        : "r"(af[b][mt][0]), "r"(af[b][mt][1]),
                          "r"(af[b][mt][2]), "r"(af[b][mt][3]),
                          "r"(bf[b][nt >> 1][(nt & 1) * 2]),
                          "r"(bf[b][nt >> 1][(nt & 1) * 2 + 1]));
                }
        }
        __syncthreads();
    }

    const int g = lane >> 2, tig = lane & 3;
    // ---- row maxes: reg p covers row wm + mt*16 + g + p*8 (2 cols/half2)
    #pragma unroll
    for (int mt = 0; mt < 4; mt++)
        #pragma unroll
        for (int p = 0; p < 2; p++) {
            float m = -2.f;
            #pragma unroll
            for (int nt = 0; nt < 8; nt++) {
                float2 f = __half22float2(*(__half2*)&acc[mt][nt][p]);
                m = fmaxf(m, fmaxf(f.x, f.y));
            }
            m = fmaxf(m, __shfl_xor_sync(0xffffffffu, m, 1));
            m = fmaxf(m, __shfl_xor_sync(0xffffffffu, m, 2));
            if (tig == 0) atomicMaxF(&srow[wm + mt * 16 + g + p * 8], m);
        }
    // ---- col maxes: col = wn64 + nt*8 + tig*2 + q (q = half index)
    #pragma unroll
    for (int nt = 0; nt < 8; nt++)
        #pragma unroll
        for (int q = 0; q < 2; q++) {
            float m = -2.f;
            #pragma unroll
            for (int mt = 0; mt < 4; mt++) {
                float2 f0 = __half22float2(*(__half2*)&acc[mt][nt][0]);
                float2 f1 = __half22float2(*(__half2*)&acc[mt][nt][1]);
                m = fmaxf(m, q ? fmaxf(f0.y, f1.y) : fmaxf(f0.x, f1.x));
            }
            m = fmaxf(m, __shfl_xor_sync(0xffffffffu, m, 4));
            m = fmaxf(m, __shfl_xor_sync(0xffffffffu, m, 8));
            m = fmaxf(m, __shfl_xor_sync(0xffffffffu, m, 16));
            if (g == 0) atomicMaxF(&scol[wn64 + nt * 8 + tig * 2 + q], m);
        }

    __syncthreads();
    if (tid < BM) atomicMaxF(&g_rowmax[m0 + tid], srow[tid]);
    if (tid < BN) atomicMaxF(&g_colmax[n0 + tid], scol[tid]);

    // ---- fused finalize: last CTA computes the entropy sums ----
    __threadfence();
    if (tid == 0) is_last = (atomicAdd(&g_done, 1) == NCTA - 1) ? 1 : 0;
    __syncthreads();
    if (!is_last) return;

    const float LOG_NORM = -0.69579514f;  // -log(0.8) - 0.5*log(2*pi)
    const float INV2S2   = 0.78125f;      // 1 / (2 * 0.8^2)
    float s1 = 0.f, s2 = 0.f;
    for (int i = tid; i < NROWS; i += 256) {
        float c = __int_as_float(__ldcg((int*)&g_rowmax[i]));
        float lp = -(c * c) * INV2S2 + LOG_NORM;
        s1 -= __expf(lp) * lp;
        c = __int_as_float(__ldcg((int*)&g_colmax[i]));
        lp = -(c * c) * INV2S2 + LOG_NORM;
        s2 -= __expf(lp) * lp;
    }
    #pragma unroll
    for (int o = 16; o > 0; o >>= 1) {
        s1 += __shfl_xor_sync(0xffffffffu, s1, o);
        s2 += __shfl_xor_sync(0xffffffffu, s2, o);
    }
    __shared__ float w1[8], w2[8];
    if ((tid & 31) == 0) { w1[tid >> 5] = s1; w2[tid >> 5] = s2; }
    __syncthreads();
    if (tid == 0) {
        float t1 = 0.f, t2 = 0.f;
        #pragma unroll
        for (int i = 0; i < 8; i++) { t1 += w1[i]; t2 += w2[i]; }
        out[0] = t1;
        out[1] = t2;
    }
}

// ---------------------------------------------------------------------------
extern "C" void kernel_launch(void* const* d_in, const int* in_sizes, int n_in,
                              void* d_out, int out_size) {
    (void)in_sizes; (void)n_in; (void)out_size;
    const float* ex = (const float*)d_in[0];
    const float* ey = (const float*)d_in[1];
    float* out = (float*)d_out;

    cudaFuncSetAttribute(gemm_max_kernel,
                         cudaFuncAttributeMaxDynamicSharedMemorySize, SMEM_TOTAL);

    norm_kernel<<<2 * NROWS / 8, 256>>>(ex, ey);
    dim3 grid(NROWS / BN, NROWS / BM);   // 32 x 64
    gemm_max_kernel<<<grid, 256, SMEM_TOTAL>>>(out);
}

// round 16
// speedup vs baseline: 1.1726x; 1.0403x over previous
#include <cuda_runtime.h>
#include <cuda_fp16.h>
#include <cstdint>
#include <math.h>

// C = normalize_rows(ex) @ normalize_rows(ey)^T  [8192 x 8192]
// rowmax/colmax -> entropy terms. f16 mma.sync GEMM, f16 accumulators,
// 128x128 CTA tile, 8 warps of 64x32, 3 CTAs/SM (24 warps/SM at 192 B/MMA),
// 2-stage cp.async, fused epilogue + finalize. C never materialized.

#define NROWS 8192
#define KDIM  768
#define BM 128
#define BN 128
#define BK 64                  // 64 f16 = 128B rows
#define NK (KDIM / BK)         // 12
#define A_BYTES (BM * BK * 2)  // 16384
#define B_BYTES (BN * BK * 2)  // 16384
#define STAGE_BYTES (A_BYTES + B_BYTES)     // 32768
#define SMEM_TOTAL (2 * STAGE_BYTES)        // 65536
#define NCTA ((NROWS / BM) * (NROWS / BN))  // 4096

__device__ __align__(128) __half g_Xn[NROWS * KDIM];
__device__ __align__(128) __half g_Yn[NROWS * KDIM];
__device__ float g_rowmax[NROWS];
__device__ float g_colmax[NROWS];
__device__ int g_done;

__device__ __forceinline__ void atomicMaxF(float* addr, float v) {
    if (v >= 0.f) atomicMax((int*)addr, __float_as_int(v));
    else          atomicMin((unsigned int*)addr, __float_as_uint(v));
}
__device__ __forceinline__ uint32_t s2u(const void* p) {
    return (uint32_t)__cvta_generic_to_shared(p);
}

// ---------------------------------------------------------------------------
// Kernel 1: row-normalize fp32 -> f16 (warp/row) + init max arrays.
// ---------------------------------------------------------------------------
__global__ __launch_bounds__(256) void norm_kernel(const float* __restrict__ ex,
                                                   const float* __restrict__ ey) {
    if (threadIdx.x < 8) {
        int t = blockIdx.x * 8 + threadIdx.x;
        if (t < NROWS) g_rowmax[t] = -2.f;
        else           g_colmax[t - NROWS] = -2.f;
    }
    if (blockIdx.x == 0 && threadIdx.x == 8) g_done = 0;

    int warp = threadIdx.x >> 5, lane = threadIdx.x & 31;
    int row = blockIdx.x * 8 + warp;
    const float* src;
    __half* dst;
    if (row < NROWS) { src = ex + (size_t)row * KDIM; dst = g_Xn + (size_t)row * KDIM; }
    else { row -= NROWS; src = ey + (size_t)row * KDIM; dst = g_Yn + (size_t)row * KDIM; }

    float4 v[6];
    float ss = 0.f;
    #pragma unroll
    for (int w = 0; w < 6; w++) {
        v[w] = ((const float4*)src)[lane + w * 32];
        ss += v[w].x * v[w].x + v[w].y * v[w].y + v[w].z * v[w].z + v[w].w * v[w].w;
    }
    #pragma unroll
    for (int o = 16; o > 0; o >>= 1) ss += __shfl_xor_sync(0xffffffffu, ss, o);
    float inv = 1.0f / fmaxf(sqrtf(ss), 1e-8f);
    #pragma unroll
    for (int w = 0; w < 6; w++) {
        __half2 lo = __floats2half2_rn(v[w].x * inv, v[w].y * inv);
        __half2 hi = __floats2half2_rn(v[w].z * inv, v[w].w * inv);
        uint2 packed;
        packed.x = *(uint32_t*)&lo;
        packed.y = *(uint32_t*)&hi;
        ((uint2*)dst)[lane + w * 32] = packed;
    }
}

// ---------------------------------------------------------------------------
// Kernel 2: f16 GEMM (f16 acc), 128x128 CTA tile, 8 warps = 2(m) x 4(n) of
// 64x32 tiles, BK=64, 2-stage cp.async, 3 CTAs/SM,
// fused row/col max + finalize.
// Swizzle: sw(row, kh) = row*128 + ((kh ^ (row & 7)) << 4), kh = 16B chunk.
// ---------------------------------------------------------------------------
__global__ __launch_bounds__(256, 3) void gemm_max_kernel(float* __restrict__ out) {
    extern __shared__ __align__(1024) char smem[];
    __shared__ float srow[BM];
    __shared__ float scol[BN];
    __shared__ int is_last;

    const int tid = threadIdx.x;
    const int warp = tid >> 5, lane = tid & 31;
    const int m0 = blockIdx.y * BM;
    const int n0 = blockIdx.x * BN;
    const int wm = (warp >> 2) * 64;   // 0 or 64
    const int wn = (warp & 3) * 32;    // 0,32,64,96

    if (tid < BM) srow[tid] = -2.f;
    if (tid < BN) scol[tid] = -2.f;

    // 64x32 warp tile, f16 acc: 4 mt x 4 nt x 2 regs = 32 regs.
    uint32_t acc[4][4][2];
    #pragma unroll
    for (int a = 0; a < 4; a++)
        #pragma unroll
        for (int b = 0; b < 4; b++) { acc[a][b][0] = 0u; acc[a][b][1] = 0u; }

    auto prefetch = [&](int stage, int k0, bool valid) {
        if (valid) {
            char* sa = smem + stage * STAGE_BYTES;
            char* sb = sa + A_BYTES;
            #pragma unroll
            for (int j = 0; j < 8; j++) {
                int i = tid + j * 256;  // 0..2047 chunks of 16B
                const __half* src;
                uint32_t dst;
                if (i < 1024) {         // A: 128 rows x 8 chunks
                    int row = i >> 3, kh = i & 7;
                    src = g_Xn + (size_t)(m0 + row) * KDIM + k0 + kh * 8;
                    dst = s2u(sa + row * 128 + ((kh ^ (row & 7)) << 4));
                } else {                // B: 128 rows x 8 chunks
                    int idx = i - 1024;
                    int row = idx >> 3, kh = idx & 7;
                    src = g_Yn + (size_t)(n0 + row) * KDIM + k0 + kh * 8;
                    dst = s2u(sb + row * 128 + ((kh ^ (row & 7)) << 4));
                }
                asm volatile("cp.async.cg.shared.global [%0], [%1], 16;"
                             :: "r"(dst), "l"(src));
            }
        }
        asm volatile("cp.async.commit_group;");
    };

    prefetch(0, 0, true);

    for (int it = 0; it < NK; it++) {
        asm volatile("cp.async.wait_group 0;");
        __syncthreads();
        prefetch((it + 1) & 1, (it + 1) * BK, it + 1 < NK);

        const uint32_t sa = s2u(smem) + (uint32_t)(it & 1) * STAGE_BYTES;
        const uint32_t sb = sa + A_BYTES;

        #pragma unroll
        for (int kk = 0; kk < 4; kk++) {
            uint32_t af[4][4], bf[2][4];
            #pragma unroll
            for (int mt = 0; mt < 4; mt++) {
                int row = wm + mt * 16 + (lane & 15);
                int kh = kk * 2 + (lane >> 4);
                uint32_t addr = sa + row * 128 + ((kh ^ (row & 7)) << 4);
                asm volatile(
                    "ldmatrix.sync.aligned.m8n8.x4.shared.b16 {%0,%1,%2,%3}, [%4];"
                    : "=r"(af[mt][0]), "=r"(af[mt][1]),
                      "=r"(af[mt][2]), "=r"(af[mt][3]) : "r"(addr));
            }
            #pragma unroll
            for (int p = 0; p < 2; p++) {
                int n = wn + p * 16 + ((lane >> 4) << 3) + (lane & 7);
                int kh = kk * 2 + ((lane >> 3) & 1);
                uint32_t addr = sb + n * 128 + ((kh ^ (n & 7)) << 4);
                asm volatile(
                    "ldmatrix.sync.aligned.m8n8.x4.shared.b16 {%0,%1,%2,%3}, [%4];"
                    : "=r"(bf[p][0]), "=r"(bf[p][1]),
                      "=r"(bf[p][2]), "=r"(bf[p][3]) : "r"(addr));
            }
            #pragma unroll
            for (int mt = 0; mt < 4; mt++)
                #pragma unroll
                for (int nt = 0; nt < 4; nt++) {
                    asm volatile(
                        "mma.sync.aligned.m16n8k16.row.col.f16.f16.f16.f16 "
                        "{%0,%1}, {%2,%3,%4,%5}, {%6,%7}, {%0,%1};\n"
                        : "+r"(acc[mt][nt][0]), "+r"(acc[mt][nt][1])
                        : "r"(af[mt][0]), "r"(af[mt][1]),
                          "r"(af[mt][2]), "r"(af[mt][3]),
                          "r"(bf[nt >> 1][(nt & 1) * 2]),
                          "r"(bf[nt >> 1][(nt & 1) * 2 + 1]));
                }
        }
        __syncthreads();
    }

    const int g = lane >> 2, tig = lane & 3;
    // ---- row maxes: reg p covers row wm + mt*16 + g + p*8 (half2 = 2 cols)
    #pragma unroll
    for (int mt = 0; mt < 4; mt++)
        #pragma unroll
        for (int p = 0; p < 2; p++) {
            float m = -2.f;
            #pragma unroll
            for (int nt = 0; nt < 4; nt++) {
                float2 f = __half22float2(*(__half2*)&acc[mt][nt][p]);
                m = fmaxf(m, fmaxf(f.x, f.y));
            }
            m = fmaxf(m, __shfl_xor_sync(0xffffffffu, m, 1));
            m = fmaxf(m, __shfl_xor_sync(0xffffffffu, m, 2));
            if (tig == 0) atomicMaxF(&srow[wm + mt * 16 + g + p * 8], m);
        }
    // ---- col maxes: col = wn + nt*8 + tig*2 + q (q = half index)
    #pragma unroll
    for (int nt = 0; nt < 4; nt++)
        #pragma unroll
        for (int q = 0; q < 2; q++) {
            float m = -2.f;
            #pragma unroll
            for (int mt = 0; mt < 4; mt++) {
                float2 f0 = __half22float2(*(__half2*)&acc[mt][nt][0]);
                float2 f1 = __half22float2(*(__half2*)&acc[mt][nt][1]);
                m = fmaxf(m, q ? fmaxf(f0.y, f1.y) : fmaxf(f0.x, f1.x));
            }
            m = fmaxf(m, __shfl_xor_sync(0xffffffffu, m, 4));
            m = fmaxf(m, __shfl_xor_sync(0xffffffffu, m, 8));
            m = fmaxf(m, __shfl_xor_sync(0xffffffffu, m, 16));
            if (g == 0) atomicMaxF(&scol[wn + nt * 8 + tig * 2 + q], m);
        }

    __syncthreads();
    if (tid < BM) atomicMaxF(&g_rowmax[m0 + tid], srow[tid]);
    if (tid < BN) atomicMaxF(&g_colmax[n0 + tid], scol[tid]);

    // ---- fused finalize: last CTA computes the entropy sums ----
    __threadfence();
    if (tid == 0) is_last = (atomicAdd(&g_done, 1) == NCTA - 1) ? 1 : 0;
    __syncthreads();
    if (!is_last) return;

    const float LOG_NORM = -0.69579514f;  // -log(0.8) - 0.5*log(2*pi)
    const float INV2S2   = 0.78125f;      // 1 / (2 * 0.8^2)
    float s1 = 0.f, s2 = 0.f;
    for (int i = tid; i < NROWS; i += 256) {
        float c = __int_as_float(__ldcg((int*)&g_rowmax[i]));
        float lp = -(c * c) * INV2S2 + LOG_NORM;
        s1 -= __expf(lp) * lp;
        c = __int_as_float(__ldcg((int*)&g_colmax[i]));
        lp = -(c * c) * INV2S2 + LOG_NORM;
        s2 -= __expf(lp) * lp;
    }
    #pragma unroll
    for (int o = 16; o > 0; o >>= 1) {
        s1 += __shfl_xor_sync(0xffffffffu, s1, o);
        s2 += __shfl_xor_sync(0xffffffffu, s2, o);
    }
    __shared__ float w1[8], w2[8];
    if ((tid & 31) == 0) { w1[tid >> 5] = s1; w2[tid >> 5] = s2; }
    __syncthreads();
    if (tid == 0) {
        float t1 = 0.f, t2 = 0.f;
        #pragma unroll
        for (int i = 0; i < 8; i++) { t1 += w1[i]; t2 += w2[i]; }
        out[0] = t1;
        out[1] = t2;
    }
}

// ---------------------------------------------------------------------------
extern "C" void kernel_launch(void* const* d_in, const int* in_sizes, int n_in,
                              void* d_out, int out_size) {
    (void)in_sizes; (void)n_in; (void)out_size;
    const float* ex = (const float*)d_in[0];
    const float* ey = (const float*)d_in[1];
    float* out = (float*)d_out;

    cudaFuncSetAttribute(gemm_max_kernel,
                         cudaFuncAttributeMaxDynamicSharedMemorySize, SMEM_TOTAL);

    norm_kernel<<<2 * NROWS / 8, 256>>>(ex, ey);
    dim3 grid(NROWS / BN, NROWS / BM);   // 64 x 64
    gemm_max_kernel<<<grid, 256, SMEM_TOTAL>>>(out);
}

// round 17
// speedup vs baseline: 1.1753x; 1.0023x over previous
#include <cuda_runtime.h>
#include <cuda_fp16.h>
#include <cstdint>
#include <math.h>

// C = normalize_rows(ex) @ normalize_rows(ey)^T  [8192 x 8192]
// rowmax/colmax -> entropy terms. f16 mma.sync GEMM, f16 accumulators,
// 128x128 CTA tile, 8 warps of 64x32, 3 CTAs/SM (24 warps/SM, 192 B/MMA),
// 2-stage cp.async with SINGLE barrier per iteration, fused epilogue +
// finalize. C never materialized.

#define NROWS 8192
#define KDIM  768
#define BM 128
#define BN 128
#define BK 64                  // 64 f16 = 128B rows
#define NK (KDIM / BK)         // 12
#define A_BYTES (BM * BK * 2)  // 16384
#define B_BYTES (BN * BK * 2)  // 16384
#define STAGE_BYTES (A_BYTES + B_BYTES)     // 32768
#define SMEM_TOTAL (2 * STAGE_BYTES)        // 65536
#define NCTA ((NROWS / BM) * (NROWS / BN))  // 4096

__device__ __align__(128) __half g_Xn[NROWS * KDIM];
__device__ __align__(128) __half g_Yn[NROWS * KDIM];
__device__ float g_rowmax[NROWS];
__device__ float g_colmax[NROWS];
__device__ int g_done;

__device__ __forceinline__ void atomicMaxF(float* addr, float v) {
    if (v >= 0.f) atomicMax((int*)addr, __float_as_int(v));
    else          atomicMin((unsigned int*)addr, __float_as_uint(v));
}
__device__ __forceinline__ uint32_t s2u(const void* p) {
    return (uint32_t)__cvta_generic_to_shared(p);
}

// ---------------------------------------------------------------------------
// Kernel 1: row-normalize fp32 -> f16 (warp/row) + init max arrays.
// ---------------------------------------------------------------------------
__global__ __launch_bounds__(256) void norm_kernel(const float* __restrict__ ex,
                                                   const float* __restrict__ ey) {
    if (threadIdx.x < 8) {
        int t = blockIdx.x * 8 + threadIdx.x;
        if (t < NROWS) g_rowmax[t] = -2.f;
        else           g_colmax[t - NROWS] = -2.f;
    }
    if (blockIdx.x == 0 && threadIdx.x == 8) g_done = 0;

    int warp = threadIdx.x >> 5, lane = threadIdx.x & 31;
    int row = blockIdx.x * 8 + warp;
    const float* src;
    __half* dst;
    if (row < NROWS) { src = ex + (size_t)row * KDIM; dst = g_Xn + (size_t)row * KDIM; }
    else { row -= NROWS; src = ey + (size_t)row * KDIM; dst = g_Yn + (size_t)row * KDIM; }

    float4 v[6];
    float ss = 0.f;
    #pragma unroll
    for (int w = 0; w < 6; w++) {
        v[w] = ((const float4*)src)[lane + w * 32];
        ss += v[w].x * v[w].x + v[w].y * v[w].y + v[w].z * v[w].z + v[w].w * v[w].w;
    }
    #pragma unroll
    for (int o = 16; o > 0; o >>= 1) ss += __shfl_xor_sync(0xffffffffu, ss, o);
    float inv = 1.0f / fmaxf(sqrtf(ss), 1e-8f);
    #pragma unroll
    for (int w = 0; w < 6; w++) {
        __half2 lo = __floats2half2_rn(v[w].x * inv, v[w].y * inv);
        __half2 hi = __floats2half2_rn(v[w].z * inv, v[w].w * inv);
        uint2 packed;
        packed.x = *(uint32_t*)&lo;
        packed.y = *(uint32_t*)&hi;
        ((uint2*)dst)[lane + w * 32] = packed;
    }
}

// ---------------------------------------------------------------------------
// Kernel 2: f16 GEMM (f16 acc), 128x128 CTA tile, 8 warps = 2(m) x 4(n) of
// 64x32 tiles, BK=64, 2-stage cp.async (ONE barrier/iter), 3 CTAs/SM,
// fused row/col max + finalize.
// Swizzle: sw(row, kh) = row*128 + ((kh ^ (row & 7)) << 4), kh = 16B chunk.
// ---------------------------------------------------------------------------
__global__ __launch_bounds__(256, 3) void gemm_max_kernel(float* __restrict__ out) {
    extern __shared__ __align__(1024) char smem[];
    __shared__ float srow[BM];
    __shared__ float scol[BN];
    __shared__ int is_last;

    const int tid = threadIdx.x;
    const int warp = tid >> 5, lane = tid & 31;
    const int m0 = blockIdx.y * BM;
    const int n0 = blockIdx.x * BN;
    const int wm = (warp >> 2) * 64;   // 0 or 64
    const int wn = (warp & 3) * 32;    // 0,32,64,96

    if (tid < BM) srow[tid] = -2.f;
    if (tid < BN) scol[tid] = -2.f;

    // 64x32 warp tile, f16 acc: 4 mt x 4 nt x 2 regs = 32 regs.
    uint32_t acc[4][4][2];
    #pragma unroll
    for (int a = 0; a < 4; a++)
        #pragma unroll
        for (int b = 0; b < 4; b++) { acc[a][b][0] = 0u; acc[a][b][1] = 0u; }

    auto prefetch = [&](int stage, int k0, bool valid) {
        if (valid) {
            char* sa = smem + stage * STAGE_BYTES;
            char* sb = sa + A_BYTES;
            #pragma unroll
            for (int j = 0; j < 8; j++) {
                int i = tid + j * 256;  // 0..2047 chunks of 16B
                const __half* src;
                uint32_t dst;
                if (i < 1024) {         // A: 128 rows x 8 chunks
                    int row = i >> 3, kh = i & 7;
                    src = g_Xn + (size_t)(m0 + row) * KDIM + k0 + kh * 8;
                    dst = s2u(sa + row * 128 + ((kh ^ (row & 7)) << 4));
                } else {                // B: 128 rows x 8 chunks
                    int idx = i - 1024;
                    int row = idx >> 3, kh = idx & 7;
                    src = g_Yn + (size_t)(n0 + row) * KDIM + k0 + kh * 8;
                    dst = s2u(sb + row * 128 + ((kh ^ (row & 7)) << 4));
                }
                asm volatile("cp.async.cg.shared.global [%0], [%1], 16;"
                             :: "r"(dst), "l"(src));
            }
        }
        asm volatile("cp.async.commit_group;");
    };

    prefetch(0, 0, true);

    for (int it = 0; it < NK; it++) {
        asm volatile("cp.async.wait_group 0;");
        __syncthreads();
        // Single barrier per iter: the prefetch below writes stage (it+1)&1,
        // which was consumed at iter it-1; every thread passed THIS barrier
        // after finishing that compute, so reads precede these writes.
        prefetch((it + 1) & 1, (it + 1) * BK, it + 1 < NK);

        const uint32_t sa = s2u(smem) + (uint32_t)(it & 1) * STAGE_BYTES;
        const uint32_t sb = sa + A_BYTES;

        #pragma unroll
        for (int kk = 0; kk < 4; kk++) {
            uint32_t af[4][4], bf[2][4];
            #pragma unroll
            for (int mt = 0; mt < 4; mt++) {
                int row = wm + mt * 16 + (lane & 15);
                int kh = kk * 2 + (lane >> 4);
                uint32_t addr = sa + row * 128 + ((kh ^ (row & 7)) << 4);
                asm volatile(
                    "ldmatrix.sync.aligned.m8n8.x4.shared.b16 {%0,%1,%2,%3}, [%4];"
                    : "=r"(af[mt][0]), "=r"(af[mt][1]),
                      "=r"(af[mt][2]), "=r"(af[mt][3]) : "r"(addr));
            }
            #pragma unroll
            for (int p = 0; p < 2; p++) {
                int n = wn + p * 16 + ((lane >> 4) << 3) + (lane & 7);
                int kh = kk * 2 + ((lane >> 3) & 1);
                uint32_t addr = sb + n * 128 + ((kh ^ (n & 7)) << 4);
                asm volatile(
                    "ldmatrix.sync.aligned.m8n8.x4.shared.b16 {%0,%1,%2,%3}, [%4];"
                    : "=r"(bf[p][0]), "=r"(bf[p][1]),
                      "=r"(bf[p][2]), "=r"(bf[p][3]) : "r"(addr));
            }
            #pragma unroll
            for (int mt = 0; mt < 4; mt++)
                #pragma unroll
                for (int nt = 0; nt < 4; nt++) {
                    asm volatile(
                        "mma.sync.aligned.m16n8k16.row.col.f16.f16.f16.f16 "
                        "{%0,%1}, {%2,%3,%4,%5}, {%6,%7}, {%0,%1};\n"
                        : "+r"(acc[mt][nt][0]), "+r"(acc[mt][nt][1])
                        : "r"(af[mt][0]), "r"(af[mt][1]),
                          "r"(af[mt][2]), "r"(af[mt][3]),
                          "r"(bf[nt >> 1][(nt & 1) * 2]),
                          "r"(bf[nt >> 1][(nt & 1) * 2 + 1]));
                }
        }
    }
    __syncthreads();

    const int g = lane >> 2, tig = lane & 3;
    // ---- row maxes: reg p covers row wm + mt*16 + g + p*8 (half2 = 2 cols)
    #pragma unroll
    for (int mt = 0; mt < 4; mt++)
        #pragma unroll
        for (int p = 0; p < 2; p++) {
            float m = -2.f;
            #pragma unroll
            for (int nt = 0; nt < 4; nt++) {
                float2 f = __half22float2(*(__half2*)&acc[mt][nt][p]);
                m = fmaxf(m, fmaxf(f.x, f.y));
            }
            m = fmaxf(m, __shfl_xor_sync(0xffffffffu, m, 1));
            m = fmaxf(m, __shfl_xor_sync(0xffffffffu, m, 2));
            if (tig == 0) atomicMaxF(&srow[wm + mt * 16 + g + p * 8], m);
        }
    // ---- col maxes: col = wn + nt*8 + tig*2 + q (q = half index)
    #pragma unroll
    for (int nt = 0; nt < 4; nt++)
        #pragma unroll
        for (int q = 0; q < 2; q++) {
            float m = -2.f;
            #pragma unroll
            for (int mt = 0; mt < 4; mt++) {
                float2 f0 = __half22float2(*(__half2*)&acc[mt][nt][0]);
                float2 f1 = __half22float2(*(__half2*)&acc[mt][nt][1]);
                m = fmaxf(m, q ? fmaxf(f0.y, f1.y) : fmaxf(f0.x, f1.x));
            }
            m = fmaxf(m, __shfl_xor_sync(0xffffffffu, m, 4));
            m = fmaxf(m, __shfl_xor_sync(0xffffffffu, m, 8));
            m = fmaxf(m, __shfl_xor_sync(0xffffffffu, m, 16));
            if (g == 0) atomicMaxF(&scol[wn + nt * 8 + tig * 2 + q], m);
        }

    __syncthreads();
    if (tid < BM) atomicMaxF(&g_rowmax[m0 + tid], srow[tid]);
    if (tid < BN) atomicMaxF(&g_colmax[n0 + tid], scol[tid]);

    // ---- fused finalize: last CTA computes the entropy sums ----
    __threadfence();
    if (tid == 0) is_last = (atomicAdd(&g_done, 1) == NCTA - 1) ? 1 : 0;
    __syncthreads();
    if (!is_last) return;

    const float LOG_NORM = -0.69579514f;  // -log(0.8) - 0.5*log(2*pi)
    const float INV2S2   = 0.78125f;      // 1 / (2 * 0.8^2)
    float s1 = 0.f, s2 = 0.f;
    for (int i = tid; i < NROWS; i += 256) {
        float c = __int_as_float(__ldcg((int*)&g_rowmax[i]));
        float lp = -(c * c) * INV2S2 + LOG_NORM;
        s1 -= __expf(lp) * lp;
        c = __int_as_float(__ldcg((int*)&g_colmax[i]));
        lp = -(c * c) * INV2S2 + LOG_NORM;
        s2 -= __expf(lp) * lp;
    }
    #pragma unroll
    for (int o = 16; o > 0; o >>= 1) {
        s1 += __shfl_xor_sync(0xffffffffu, s1, o);
        s2 += __shfl_xor_sync(0xffffffffu, s2, o);
    }
    __shared__ float w1[8], w2[8];
    if ((tid & 31) == 0) { w1[tid >> 5] = s1; w2[tid >> 5] = s2; }
    __syncthreads();
    if (tid == 0) {
        float t1 = 0.f, t2 = 0.f;
        #pragma unroll
        for (int i = 0; i < 8; i++) { t1 += w1[i]; t2 += w2[i]; }
        out[0] = t1;
        out[1] = t2;
    }
}

// ---------------------------------------------------------------------------
extern "C" void kernel_launch(void* const* d_in, const int* in_sizes, int n_in,
                              void* d_out, int out_size) {
    (void)in_sizes; (void)n_in; (void)out_size;
    const float* ex = (const float*)d_in[0];
    const float* ey = (const float*)d_in[1];
    float* out = (float*)d_out;

    cudaFuncSetAttribute(gemm_max_kernel,
                         cudaFuncAttributeMaxDynamicSharedMemorySize, SMEM_TOTAL);

    norm_kernel<<<2 * NROWS / 8, 256>>>(ex, ey);
    dim3 grid(NROWS / BN, NROWS / BM);   // 64 x 64
    gemm_max_kernel<<<grid, 256, SMEM_TOTAL>>>(out);
}